// round 4
// baseline (speedup 1.0000x reference)
#include <cuda_runtime.h>
#include <math.h>

#define B_      32
#define CIN     2048
#define NPIX    625        // 25*25
#define NANC    9
#define HID     9
#define NPOS    2048
#define NNEG    2048
#define NENT    4096
#define CCHUNK  128        // channels per block
#define CSUB    16         // channels per smem stage
#define NCHUNK  (CIN/CCHUNK)   // 16
#define MAXINST 256
#define WROW    12         // padded taps per hid (9 -> 12 for float4)

// Scratch (device globals: no allocation allowed)
__device__ float d_H[NENT * HID];            // partial hidden sums (pre-bias, pre-relu)
__device__ float d_Wp[CIN * HID * WROW];     // repacked weights [c][hid][12]

// ---------------- K0: zero accumulator + repack Wh [9][2048][3][3] -> [c][hid][12]
__global__ void k_prep(const float* __restrict__ Wh) {
    int idx = blockIdx.x * blockDim.x + threadIdx.x;
    if (idx < CIN * HID * WROW) {
        int c   = idx / (HID * WROW);
        int r   = idx % (HID * WROW);
        int hid = r / WROW;
        int tap = r % WROW;
        d_Wp[idx] = (tap < 9) ? Wh[(hid * CIN + c) * 9 + tap] : 0.f;
    }
    if (idx < NENT * HID) d_H[idx] = 0.f;
}

// ---------------- K1: sparse 3x3 conv partial sums.
// grid = (32 images, 16 c-chunks); block = 256 threads.
// Each block streams F[b, c0:c0+128, :, :] (contiguous in NCHW) through smem in
// stages of 16 channels, and accumulates hidden[9] partials for every gathered
// entry belonging to image b. Thread layout: slot = tid&127 (entry instance,
// same across a warp's c so weight LDS broadcasts), half = tid>>7 (c split).
__global__ void __launch_bounds__(256) k_conv(
    const float* __restrict__ F,
    const int* __restrict__ posi,
    const int* __restrict__ negi)
{
    __shared__ float sF[CSUB * NPIX];          // 40000 B
    __shared__ float sW[CSUB * HID * WROW];    // 6912 B
    __shared__ unsigned short s_pos[MAXINST];  // y*32 + x
    __shared__ unsigned short s_ent[MAXINST];  // entry id 0..4095
    __shared__ int s_cnt;

    const int b   = blockIdx.x;
    const int c0  = blockIdx.y * CCHUNK;
    const int tid = threadIdx.x;

    if (tid == 0) s_cnt = 0;
    __syncthreads();

    // scan the 4096 entries, keep those in image b
    for (int e = tid; e < NENT; e += 256) {
        int flat = (e < NPOS) ? posi[e] : negi[e - NPOS];
        int be = flat / (NPIX * NANC);
        if (be == b) {
            int slot = atomicAdd(&s_cnt, 1);
            if (slot < MAXINST) {
                int rem = flat % (NPIX * NANC);
                int pix = rem / NANC;
                int y = pix / 25, x = pix - y * 25;
                s_pos[slot] = (unsigned short)((y << 5) | x);
                s_ent[slot] = (unsigned short)e;
            }
        }
    }
    __syncthreads();
    const int ninst = min(s_cnt, MAXINST);
    if (ninst == 0) return;   // uniform across block

    const int slot = tid & 127;
    const int half = tid >> 7;   // 0/1 -> channels [half*8, half*8+8) within each stage

    // two instances per thread: A = slot, B = slot+128
    int yA = 0, xA = 0, yB = 0, xB = 0;
    const bool vA = (slot < ninst);
    const bool vB = (slot + 128 < ninst);
    if (vA) { int p = s_pos[slot];       yA = p >> 5; xA = p & 31; }
    if (vB) { int p = s_pos[slot + 128]; yB = p >> 5; xB = p & 31; }

    const int baseA = (yA - 1) * 25 + (xA - 1);
    const int baseB = (yB - 1) * 25 + (xB - 1);
    unsigned mA = 0, mB = 0;
    #pragma unroll
    for (int t = 0; t < 9; t++) {
        int dy = t / 3, dx = t % 3;
        if (vA && (unsigned)(yA - 1 + dy) < 25u && (unsigned)(xA - 1 + dx) < 25u) mA |= 1u << t;
        if (vB && (unsigned)(yB - 1 + dy) < 25u && (unsigned)(xB - 1 + dx) < 25u) mB |= 1u << t;
    }

    float accA[HID], accB[HID];
    #pragma unroll
    for (int h = 0; h < HID; h++) { accA[h] = 0.f; accB[h] = 0.f; }

    for (int cc = 0; cc < CCHUNK; cc += CSUB) {
        __syncthreads();  // previous-stage compute done before overwrite
        // stage F: contiguous 16*625 floats (c-major rows are contiguous in NCHW)
        const float* gF = F + ((size_t)b * CIN + (c0 + cc)) * NPIX;
        for (int i = tid; i < CSUB * NPIX; i += 256) sF[i] = gF[i];
        const float* gW = d_Wp + (size_t)(c0 + cc) * (HID * WROW);
        for (int i = tid; i < CSUB * HID * WROW; i += 256) sW[i] = gW[i];
        __syncthreads();

        #pragma unroll
        for (int k8 = 0; k8 < 8; k8++) {
            const int k = half * 8 + k8;
            const float* fr = sF + k * NPIX;
            float pA[9], pB[9];
            #pragma unroll
            for (int t = 0; t < 9; t++) {
                int dy = t / 3, dx = t - dy * 3;
                pA[t] = (mA >> t & 1u) ? fr[baseA + dy * 25 + dx] : 0.f;
                pB[t] = (mB >> t & 1u) ? fr[baseB + dy * 25 + dx] : 0.f;
            }
            const float4* wr = (const float4*)(sW + k * (HID * WROW));
            #pragma unroll
            for (int h = 0; h < HID; h++) {
                float4 w0 = wr[h * 3 + 0];
                float4 w1 = wr[h * 3 + 1];
                float4 w2 = wr[h * 3 + 2];
                float a = accA[h];
                a = fmaf(pA[0], w0.x, a); a = fmaf(pA[1], w0.y, a); a = fmaf(pA[2], w0.z, a);
                a = fmaf(pA[3], w0.w, a); a = fmaf(pA[4], w1.x, a); a = fmaf(pA[5], w1.y, a);
                a = fmaf(pA[6], w1.z, a); a = fmaf(pA[7], w1.w, a); a = fmaf(pA[8], w2.x, a);
                accA[h] = a;
                float bacc = accB[h];
                bacc = fmaf(pB[0], w0.x, bacc); bacc = fmaf(pB[1], w0.y, bacc); bacc = fmaf(pB[2], w0.z, bacc);
                bacc = fmaf(pB[3], w0.w, bacc); bacc = fmaf(pB[4], w1.x, bacc); bacc = fmaf(pB[5], w1.y, bacc);
                bacc = fmaf(pB[6], w1.z, bacc); bacc = fmaf(pB[7], w1.w, bacc); bacc = fmaf(pB[8], w2.x, bacc);
                accB[h] = bacc;
            }
        }
    }

    // reduce the two c-halves through smem (reuse sF), then atomically accumulate
    __syncthreads();
    float* red = sF;   // 256*9 floats = 9216 B < 40000 B
    if (half == 1) {
        #pragma unroll
        for (int h = 0; h < HID; h++) {
            red[slot * HID + h]        = accA[h];
            red[(slot + 128) * HID + h] = accB[h];
        }
    }
    __syncthreads();
    if (half == 0) {
        if (vA) {
            int e = s_ent[slot];
            #pragma unroll
            for (int h = 0; h < HID; h++)
                atomicAdd(&d_H[e * HID + h], accA[h] + red[slot * HID + h]);
        }
        if (vB) {
            int e = s_ent[slot + 128];
            #pragma unroll
            for (int h = 0; h < HID; h++)
                atomicAdd(&d_H[e * HID + h], accB[h] + red[(slot + 128) * HID + h]);
        }
    }
}

// ---------------- K2: bias + relu + 1x1 convs + box decode -> outputs
// out layout: [0,2048) pos_conf | [2048,4096) neg_conf |
//             [4096,12288) pos_offsets[2048][4] | [12288,20480) proposals[2048][4]
__global__ void k_final(const int* __restrict__ posi, const int* __restrict__ negi,
                        const float* __restrict__ pos_ancs,
                        const float* __restrict__ bh,
                        const float* __restrict__ Wc, const float* __restrict__ bc,
                        const float* __restrict__ Wr, const float* __restrict__ br,
                        float* __restrict__ out)
{
    int e = blockIdx.x * blockDim.x + threadIdx.x;
    if (e >= NENT) return;
    int flat = (e < NPOS) ? posi[e] : negi[e - NPOS];
    int anc = flat % NANC;

    float h[HID];
    #pragma unroll
    for (int i = 0; i < HID; i++) h[i] = fmaxf(d_H[e * HID + i] + bh[i], 0.f);

    float conf = bc[anc];
    #pragma unroll
    for (int i = 0; i < HID; i++) conf = fmaf(Wc[anc * HID + i], h[i], conf);
    out[e] = conf;

    if (e < NPOS) {
        float off[4];
        #pragma unroll
        for (int j = 0; j < 4; j++) {
            int r = anc * 4 + j;
            float s = br[r];
            #pragma unroll
            for (int i = 0; i < HID; i++) s = fmaf(Wr[r * HID + i], h[i], s);
            off[j] = s;
            out[4096 + e * 4 + j] = s;
        }
        const float* pa = pos_ancs + e * 4;
        float cx = (pa[0] + pa[2]) * 0.5f;
        float cy = (pa[1] + pa[3]) * 0.5f;
        float w  = pa[2] - pa[0];
        float hh = pa[3] - pa[1];
        float ncx = fmaf(off[0], w,  cx);
        float ncy = fmaf(off[1], hh, cy);
        float nw  = w  * expf(off[2]);
        float nh  = hh * expf(off[3]);
        out[12288 + e * 4 + 0] = ncx - nw * 0.5f;
        out[12288 + e * 4 + 1] = ncy - nh * 0.5f;
        out[12288 + e * 4 + 2] = ncx + nw * 0.5f;
        out[12288 + e * 4 + 3] = ncy + nh * 0.5f;
    }
}

extern "C" void kernel_launch(void* const* d_in, const int* in_sizes, int n_in,
                              void* d_out, int out_size) {
    const float* F   = (const float*)d_in[0];
    const int*   pi  = (const int*)  d_in[1];
    const int*   ni  = (const int*)  d_in[2];
    const float* pa  = (const float*)d_in[3];
    const float* Wh  = (const float*)d_in[4];
    const float* bh  = (const float*)d_in[5];
    const float* Wc  = (const float*)d_in[6];
    const float* bc  = (const float*)d_in[7];
    const float* Wr  = (const float*)d_in[8];
    const float* br  = (const float*)d_in[9];
    float* out = (float*)d_out;

    k_prep<<<(CIN * HID * WROW + 255) / 256, 256>>>(Wh);
    dim3 grid(B_, NCHUNK);
    k_conv<<<grid, 256>>>(F, pi, ni);
    k_final<<<(NENT + 255) / 256, 256>>>(pi, ni, pa, bh, Wc, bc, Wr, br, out);
}

// round 5
// speedup vs baseline: 1.0118x; 1.0118x over previous
#include <cuda_runtime.h>
#include <math.h>

#define B_      32
#define CIN     2048
#define NPIX    625        // 25*25
#define NANC    9
#define HID     9
#define NPOS    2048
#define NENT    4096
#define CCHUNK  128        // channels per block
#define CSUB    16         // channels per smem stage
#define NCHUNK  (CIN/CCHUNK)   // 16
#define MAXINST 256
#define WROW    12         // padded taps per hid (9 -> 12 for float4)

// Scratch (device globals: no allocation allowed)
// Partial hidden sums per channel-chunk: fully written each run (no zeroing needed).
__device__ float d_part[NCHUNK * NENT * HID];

// Per-channel accumulate: one instance pair (A always, B guarded warp-uniformly),
// HC hidden channels starting at HB. Weights read as broadcast float4 from smem.
template<int HB, int HC>
__device__ __forceinline__ void accum_chan(
    const float* __restrict__ fr, const float* __restrict__ wbase,
    int baseA, unsigned mA, int baseB, unsigned mB, bool doB,
    float accA[5], float accB[5])
{
    float pA[9], pB[9];
#pragma unroll
    for (int t = 0; t < 9; t++) {
        int dy = t / 3, dx = t - dy * 3;
        pA[t] = (mA >> t & 1u) ? fr[baseA + dy * 25 + dx] : 0.f;
        pB[t] = (doB && (mB >> t & 1u)) ? fr[baseB + dy * 25 + dx] : 0.f;
    }
    const float4* wk = (const float4*)wbase;
#pragma unroll
    for (int j = 0; j < HC; j++) {
        float4 w0 = wk[(HB + j) * 3 + 0];
        float4 w1 = wk[(HB + j) * 3 + 1];
        float4 w2 = wk[(HB + j) * 3 + 2];
        float a = accA[j];
        a = fmaf(pA[0], w0.x, a); a = fmaf(pA[1], w0.y, a); a = fmaf(pA[2], w0.z, a);
        a = fmaf(pA[3], w0.w, a); a = fmaf(pA[4], w1.x, a); a = fmaf(pA[5], w1.y, a);
        a = fmaf(pA[6], w1.z, a); a = fmaf(pA[7], w1.w, a); a = fmaf(pA[8], w2.x, a);
        accA[j] = a;
        if (doB) {
            float c = accB[j];
            c = fmaf(pB[0], w0.x, c); c = fmaf(pB[1], w0.y, c); c = fmaf(pB[2], w0.z, c);
            c = fmaf(pB[3], w0.w, c); c = fmaf(pB[4], w1.x, c); c = fmaf(pB[5], w1.y, c);
            c = fmaf(pB[6], w1.z, c); c = fmaf(pB[7], w1.w, c); c = fmaf(pB[8], w2.x, c);
            accB[j] = c;
        }
    }
}

// ---------------- K1: sparse 3x3 conv partial sums.
// grid = (32 images, 16 c-chunks); block = 256 threads.
// Thread layout: slot = tid&127 (instance), hh = tid>>7 (hid half: 0 -> h0..3, 1 -> h4..8).
// Each thread walks ALL 128 channels of its chunk; no wasted FMA lanes.
__global__ void __launch_bounds__(256) k_conv(
    const float* __restrict__ F,
    const float* __restrict__ Wh,
    const int* __restrict__ posi,
    const int* __restrict__ negi)
{
    __shared__ float sF[CSUB * NPIX];          // 40000 B
    __shared__ float sW[CSUB * HID * WROW];    // 6912 B
    __shared__ unsigned short s_pos[MAXINST];  // y*32 + x
    __shared__ unsigned short s_ent[MAXINST];  // entry id 0..4095
    __shared__ int s_cnt;

    const int b     = blockIdx.x;
    const int chunk = blockIdx.y;
    const int c0    = chunk * CCHUNK;
    const int tid   = threadIdx.x;

    if (tid == 0) s_cnt = 0;
    __syncthreads();

    // scan the 4096 entries, keep those in image b
    for (int e = tid; e < NENT; e += 256) {
        int flat = (e < NPOS) ? posi[e] : negi[e - NPOS];
        int be = flat / (NPIX * NANC);
        if (be == b) {
            int slot = atomicAdd(&s_cnt, 1);
            if (slot < MAXINST) {
                int rem = flat % (NPIX * NANC);
                int pix = rem / NANC;
                int y = pix / 25, x = pix - y * 25;
                s_pos[slot] = (unsigned short)((y << 5) | x);
                s_ent[slot] = (unsigned short)e;
            }
        }
    }
    __syncthreads();
    const int ninst = min(s_cnt, MAXINST);
    if (ninst == 0) return;   // uniform across block

    const int slot = tid & 127;
    const int hh   = tid >> 7;   // 0: h 0..3, 1: h 4..8

    for (int base0 = 0; base0 < ninst; base0 += 2 * 128) {
        const int iA = base0 + slot;
        const int iB = base0 + 128 + slot;
        const bool vA = (iA < ninst);
        const bool vB = (iB < ninst);
        // warp-uniform: does ANY lane of this warp own a valid B instance?
        const bool doB = (base0 + 128 + (slot & ~31)) < ninst;

        int yA = 0, xA = 0, yB = 0, xB = 0, eA = 0, eB = 0;
        if (vA) { int p = s_pos[iA]; yA = p >> 5; xA = p & 31; eA = s_ent[iA]; }
        if (vB) { int p = s_pos[iB]; yB = p >> 5; xB = p & 31; eB = s_ent[iB]; }
        const int baseA = (yA - 1) * 25 + (xA - 1);
        const int baseB = (yB - 1) * 25 + (xB - 1);
        unsigned mA = 0, mB = 0;
#pragma unroll
        for (int t = 0; t < 9; t++) {
            int dy = t / 3, dx = t % 3;
            if (vA && (unsigned)(yA - 1 + dy) < 25u && (unsigned)(xA - 1 + dx) < 25u) mA |= 1u << t;
            if (vB && (unsigned)(yB - 1 + dy) < 25u && (unsigned)(xB - 1 + dx) < 25u) mB |= 1u << t;
        }

        float accA[5] = {0.f, 0.f, 0.f, 0.f, 0.f};
        float accB[5] = {0.f, 0.f, 0.f, 0.f, 0.f};

        for (int cc = 0; cc < CCHUNK; cc += CSUB) {
            __syncthreads();  // previous-stage compute done before overwrite
            // stage F: 16 contiguous channel planes; base index (b*2048+c0+cc) is a
            // multiple of 16 -> byte offset multiple of 16 -> float4-aligned.
            const float4* gF = (const float4*)(F + ((size_t)b * CIN + (c0 + cc)) * NPIX);
            float4* s4 = (float4*)sF;
            for (int i = tid; i < CSUB * NPIX / 4; i += 256) s4[i] = gF[i];
            // stage + repack weights [h][c][3][3] -> [c][h][12] (L2-resident table)
            for (int i = tid; i < CSUB * HID * WROW; i += 256) {
                int c = i / (HID * WROW);
                int r = i % (HID * WROW);
                int h = r / WROW;
                int t = r % WROW;
                sW[i] = (t < 9) ? Wh[((size_t)h * CIN + (c0 + cc + c)) * 9 + t] : 0.f;
            }
            __syncthreads();

#pragma unroll 4
            for (int k = 0; k < CSUB; k++) {
                const float* fr = sF + k * NPIX;
                const float* wb = sW + k * (HID * WROW);
                if (hh == 0) accum_chan<0, 4>(fr, wb, baseA, mA, baseB, mB, doB, accA, accB);
                else         accum_chan<4, 5>(fr, wb, baseA, mA, baseB, mB, doB, accA, accB);
            }
        }

        // direct partial store: (chunk, entry, hid) owned by exactly one thread
        float* outp = d_part + (size_t)chunk * NENT * HID;
        const int hb = hh ? 4 : 0;
        const int hc = hh ? 5 : 4;
        if (vA) {
#pragma unroll
            for (int j = 0; j < 5; j++) if (j < hc) outp[eA * HID + hb + j] = accA[j];
        }
        if (vB) {
#pragma unroll
            for (int j = 0; j < 5; j++) if (j < hc) outp[eB * HID + hb + j] = accB[j];
        }
    }
}

// ---------------- K2: sum partials + bias + relu + 1x1 convs + box decode
// out layout: [0,2048) pos_conf | [2048,4096) neg_conf |
//             [4096,12288) pos_offsets[2048][4] | [12288,20480) proposals[2048][4]
__global__ void k_final(const int* __restrict__ posi, const int* __restrict__ negi,
                        const float* __restrict__ pos_ancs,
                        const float* __restrict__ bh,
                        const float* __restrict__ Wc, const float* __restrict__ bc,
                        const float* __restrict__ Wr, const float* __restrict__ br,
                        float* __restrict__ out)
{
    int e = blockIdx.x * blockDim.x + threadIdx.x;
    if (e >= NENT) return;
    int flat = (e < NPOS) ? posi[e] : negi[e - NPOS];
    int anc = flat % NANC;

    float h[HID];
#pragma unroll
    for (int i = 0; i < HID; i++) h[i] = bh[i];
#pragma unroll
    for (int c = 0; c < NCHUNK; c++) {
        const float* p = d_part + (size_t)c * NENT * HID + e * HID;
#pragma unroll
        for (int i = 0; i < HID; i++) h[i] += p[i];
    }
#pragma unroll
    for (int i = 0; i < HID; i++) h[i] = fmaxf(h[i], 0.f);

    float conf = bc[anc];
#pragma unroll
    for (int i = 0; i < HID; i++) conf = fmaf(Wc[anc * HID + i], h[i], conf);
    out[e] = conf;

    if (e < NPOS) {
        float off[4];
#pragma unroll
        for (int j = 0; j < 4; j++) {
            int r = anc * 4 + j;
            float s = br[r];
#pragma unroll
            for (int i = 0; i < HID; i++) s = fmaf(Wr[r * HID + i], h[i], s);
            off[j] = s;
            out[4096 + e * 4 + j] = s;
        }
        const float* pa = pos_ancs + e * 4;
        float cx = (pa[0] + pa[2]) * 0.5f;
        float cy = (pa[1] + pa[3]) * 0.5f;
        float w  = pa[2] - pa[0];
        float hh2 = pa[3] - pa[1];
        float ncx = fmaf(off[0], w,   cx);
        float ncy = fmaf(off[1], hh2, cy);
        float nw  = w   * expf(off[2]);
        float nh  = hh2 * expf(off[3]);
        out[12288 + e * 4 + 0] = ncx - nw * 0.5f;
        out[12288 + e * 4 + 1] = ncy - nh * 0.5f;
        out[12288 + e * 4 + 2] = ncx + nw * 0.5f;
        out[12288 + e * 4 + 3] = ncy + nh * 0.5f;
    }
}

extern "C" void kernel_launch(void* const* d_in, const int* in_sizes, int n_in,
                              void* d_out, int out_size) {
    const float* F   = (const float*)d_in[0];
    const int*   pi  = (const int*)  d_in[1];
    const int*   ni  = (const int*)  d_in[2];
    const float* pa  = (const float*)d_in[3];
    const float* Wh  = (const float*)d_in[4];
    const float* bh  = (const float*)d_in[5];
    const float* Wc  = (const float*)d_in[6];
    const float* bc  = (const float*)d_in[7];
    const float* Wr  = (const float*)d_in[8];
    const float* br  = (const float*)d_in[9];
    float* out = (float*)d_out;

    dim3 grid(B_, NCHUNK);
    k_conv<<<grid, 256>>>(F, Wh, pi, ni);
    k_final<<<(NENT + 255) / 256, 256>>>(pi, ni, pa, bh, Wc, bc, Wr, br, out);
}

// round 6
// speedup vs baseline: 1.4269x; 1.4103x over previous
#include <cuda_runtime.h>
#include <math.h>

#define B_      32
#define CIN     2048
#define NPIX    625        // 25*25
#define NANC    9
#define HID     9
#define NPOS    2048
#define NENT    4096
#define CCHUNK  128        // channels per block
#define CSUB    16         // channels per smem stage
#define NCHUNK  (CIN/CCHUNK)   // 16
#define MAXINST 256
#define WROW    12         // padded taps per hid (9 -> 12 for float4)
#define SLOTS   64
#define ISTRIDE 192        // instances per outer sweep (3 per thread)

// Scratch (device globals: no allocation allowed)
__device__ float d_part[NCHUNK * NENT * HID];  // per-chunk partial hidden sums
__device__ float d_H[NENT * HID];              // reduced hidden sums

__device__ __constant__ int c_off[9] = {0, 1, 2, 25, 26, 27, 50, 51, 52};

// Accumulate one channel for NI instances (NI warp-uniform). All 9 hid per thread.
template<int NI>
__device__ __forceinline__ void chan_accum(
    const float* __restrict__ fr, const float4* __restrict__ wk,
    const int* pb, const unsigned* mk, float (&acc)[3][HID])
{
    float p[NI][9];
#pragma unroll
    for (int i = 0; i < NI; i++) {
#pragma unroll
        for (int t = 0; t < 9; t++)
            p[i][t] = (mk[i] >> t & 1u) ? fr[pb[i] + c_off[t]] : 0.f;
    }
#pragma unroll
    for (int h = 0; h < HID; h++) {
        float4 w0 = wk[h * 3 + 0];
        float4 w1 = wk[h * 3 + 1];
        float4 w2 = wk[h * 3 + 2];
#pragma unroll
        for (int i = 0; i < NI; i++) {
            float a = acc[i][h];
            a = fmaf(p[i][0], w0.x, a); a = fmaf(p[i][1], w0.y, a); a = fmaf(p[i][2], w0.z, a);
            a = fmaf(p[i][3], w0.w, a); a = fmaf(p[i][4], w1.x, a); a = fmaf(p[i][5], w1.y, a);
            a = fmaf(p[i][6], w1.z, a); a = fmaf(p[i][7], w1.w, a); a = fmaf(p[i][8], w2.x, a);
            acc[i][h] = a;
        }
    }
}

// ---------------- K1: sparse 3x3 conv partial sums.
// grid = (32 images, 16 c-chunks); block = 256 threads.
// Thread layout: slot = tid&63 (instance lane), cs = tid>>6 (4-way channel split).
// Instances per thread: A=slot, B=64+slot, C=128+slot (C warp-uniform guarded).
__global__ void __launch_bounds__(256) k_conv(
    const float* __restrict__ F,
    const float* __restrict__ Wh,
    const int* __restrict__ posi,
    const int* __restrict__ negi)
{
    __shared__ float sF[CSUB * NPIX];          // 40000 B (reused as reduce buffer)
    __shared__ float sW[CSUB * HID * WROW];    // 6912 B
    __shared__ unsigned short s_pos[MAXINST];  // y*32 + x
    __shared__ unsigned short s_ent[MAXINST];  // entry id 0..4095
    __shared__ int s_cnt;

    const int b     = blockIdx.x;
    const int chunk = blockIdx.y;
    const int c0    = chunk * CCHUNK;
    const int tid   = threadIdx.x;

    if (tid == 0) s_cnt = 0;
    __syncthreads();

    // scan the 4096 entries, keep those in image b
    for (int e = tid; e < NENT; e += 256) {
        int flat = (e < NPOS) ? posi[e] : negi[e - NPOS];
        int be = flat / (NPIX * NANC);
        if (be == b) {
            int slot = atomicAdd(&s_cnt, 1);
            if (slot < MAXINST) {
                int rem = flat % (NPIX * NANC);
                int pix = rem / NANC;
                int y = pix / 25, x = pix - y * 25;
                s_pos[slot] = (unsigned short)((y << 5) | x);
                s_ent[slot] = (unsigned short)e;
            }
        }
    }
    __syncthreads();
    const int ninst = min(s_cnt, MAXINST);
    if (ninst == 0) return;   // uniform across block

    const int slot = tid & (SLOTS - 1);
    const int cs   = tid >> 6;           // 0..3
    const int sg   = slot & ~31;         // warp-uniform slot group base

    for (int base = 0; base < ninst; base += ISTRIDE) {
        int  idx[3];
        bool val[3];
        int  pb[3]  = {0, 0, 0};
        int  ent[3] = {0, 0, 0};
        unsigned mk[3] = {0, 0, 0};
#pragma unroll
        for (int i = 0; i < 3; i++) {
            idx[i] = base + i * SLOTS + slot;
            val[i] = idx[i] < ninst;
            if (val[i]) {
                int p = s_pos[idx[i]];
                int y = p >> 5, x = p & 31;
                ent[i] = s_ent[idx[i]];
                pb[i]  = (y - 1) * 25 + (x - 1);
                unsigned m = 0;
#pragma unroll
                for (int t = 0; t < 9; t++) {
                    int dy = t / 3, dx = t - dy * 3;
                    if ((unsigned)(y - 1 + dy) < 25u && (unsigned)(x - 1 + dx) < 25u)
                        m |= 1u << t;
                }
                mk[i] = m;
            }
        }
        // warp-uniform active-instance count (guards are monotone: doC => doB)
        const int nact = 1 + (base + SLOTS + sg < ninst) + (base + 2 * SLOTS + sg < ninst);

        float acc[3][HID];
#pragma unroll
        for (int i = 0; i < 3; i++)
#pragma unroll
            for (int h = 0; h < HID; h++) acc[i][h] = 0.f;

        for (int cc = 0; cc < CCHUNK; cc += CSUB) {
            __syncthreads();  // previous-stage compute / reduce done before overwrite
            // stage F: 16 contiguous channel planes (float4-aligned: base idx % 16 == 0)
            const float4* gF = (const float4*)(F + ((size_t)b * CIN + (c0 + cc)) * NPIX);
            float4* s4 = (float4*)sF;
            for (int i = tid; i < CSUB * NPIX / 4; i += 256) s4[i] = gF[i];
            // stage + repack weights [h][c][3][3] -> [c][h][12] (Wh is L2-resident)
            for (int i = tid; i < CSUB * HID * WROW; i += 256) {
                int c = i / (HID * WROW);
                int r = i % (HID * WROW);
                int h = r / WROW;
                int t = r % WROW;
                sW[i] = (t < 9) ? Wh[((size_t)h * CIN + (c0 + cc + c)) * 9 + t] : 0.f;
            }
            __syncthreads();

#pragma unroll
            for (int kk = 0; kk < CSUB / 4; kk++) {
                const int k = cs * (CSUB / 4) + kk;
                const float*  fr = sF + k * NPIX;
                const float4* wk = (const float4*)(sW + k * (HID * WROW));
                if (nact == 3)      chan_accum<3>(fr, wk, pb, mk, acc);
                else if (nact == 2) chan_accum<2>(fr, wk, pb, mk, acc);
                else                chan_accum<1>(fr, wk, pb, mk, acc);
            }
        }

        // cross-csplit reduction through smem (reuse sF: 3*192*9 = 5184 floats)
        __syncthreads();
        float* red = sF;
        if (cs > 0) {
#pragma unroll
            for (int i = 0; i < 3; i++) {
                int si = i * SLOTS + slot;
#pragma unroll
                for (int h = 0; h < HID; h++)
                    red[((cs - 1) * ISTRIDE + si) * HID + h] = acc[i][h];
            }
        }
        __syncthreads();
        if (cs == 0) {
            float* outp = d_part + (size_t)chunk * NENT * HID;
#pragma unroll
            for (int i = 0; i < 3; i++) {
                if (!val[i]) continue;
                int si = i * SLOTS + slot;
#pragma unroll
                for (int h = 0; h < HID; h++) {
                    float s = acc[i][h]
                            + red[(0 * ISTRIDE + si) * HID + h]
                            + red[(1 * ISTRIDE + si) * HID + h]
                            + red[(2 * ISTRIDE + si) * HID + h];
                    outp[ent[i] * HID + h] = s;
                }
            }
        }
        __syncthreads();  // red consumed before next sweep re-stages sF
    }
}

// ---------------- K2a: reduce 16 chunk partials (coalesced)
__global__ void k_reduce() {
    int t = blockIdx.x * blockDim.x + threadIdx.x;
    if (t >= NENT * HID) return;
    float s = 0.f;
#pragma unroll
    for (int c = 0; c < NCHUNK; c++) s += d_part[(size_t)c * NENT * HID + t];
    d_H[t] = s;
}

// ---------------- K2b: bias + relu + 1x1 convs + box decode
// out layout: [0,2048) pos_conf | [2048,4096) neg_conf |
//             [4096,12288) pos_offsets[2048][4] | [12288,20480) proposals[2048][4]
__global__ void k_head(const int* __restrict__ posi, const int* __restrict__ negi,
                       const float* __restrict__ pos_ancs,
                       const float* __restrict__ bh,
                       const float* __restrict__ Wc, const float* __restrict__ bc,
                       const float* __restrict__ Wr, const float* __restrict__ br,
                       float* __restrict__ out)
{
    int e = blockIdx.x * blockDim.x + threadIdx.x;
    if (e >= NENT) return;
    int flat = (e < NPOS) ? posi[e] : negi[e - NPOS];
    int anc = flat % NANC;

    float h[HID];
#pragma unroll
    for (int i = 0; i < HID; i++) h[i] = fmaxf(d_H[e * HID + i] + bh[i], 0.f);

    float conf = bc[anc];
#pragma unroll
    for (int i = 0; i < HID; i++) conf = fmaf(Wc[anc * HID + i], h[i], conf);
    out[e] = conf;

    if (e < NPOS) {
        float off[4];
#pragma unroll
        for (int j = 0; j < 4; j++) {
            int r = anc * 4 + j;
            float s = br[r];
#pragma unroll
            for (int i = 0; i < HID; i++) s = fmaf(Wr[r * HID + i], h[i], s);
            off[j] = s;
            out[4096 + e * 4 + j] = s;
        }
        const float* pa = pos_ancs + e * 4;
        float cx = (pa[0] + pa[2]) * 0.5f;
        float cy = (pa[1] + pa[3]) * 0.5f;
        float w  = pa[2] - pa[0];
        float hh = pa[3] - pa[1];
        float ncx = fmaf(off[0], w,  cx);
        float ncy = fmaf(off[1], hh, cy);
        float nw  = w  * expf(off[2]);
        float nh  = hh * expf(off[3]);
        out[12288 + e * 4 + 0] = ncx - nw * 0.5f;
        out[12288 + e * 4 + 1] = ncy - nh * 0.5f;
        out[12288 + e * 4 + 2] = ncx + nw * 0.5f;
        out[12288 + e * 4 + 3] = ncy + nh * 0.5f;
    }
}

extern "C" void kernel_launch(void* const* d_in, const int* in_sizes, int n_in,
                              void* d_out, int out_size) {
    const float* F   = (const float*)d_in[0];
    const int*   pi  = (const int*)  d_in[1];
    const int*   ni  = (const int*)  d_in[2];
    const float* pa  = (const float*)d_in[3];
    const float* Wh  = (const float*)d_in[4];
    const float* bh  = (const float*)d_in[5];
    const float* Wc  = (const float*)d_in[6];
    const float* bc  = (const float*)d_in[7];
    const float* Wr  = (const float*)d_in[8];
    const float* br  = (const float*)d_in[9];
    float* out = (float*)d_out;

    dim3 grid(B_, NCHUNK);
    k_conv<<<grid, 256>>>(F, Wh, pi, ni);
    k_reduce<<<(NENT * HID + 255) / 256, 256>>>();
    k_head<<<(NENT + 255) / 256, 256>>>(pi, ni, pa, bh, Wc, bc, Wr, br, out);
}